// round 1
// baseline (speedup 1.0000x reference)
#include <cuda_runtime.h>
#include <cuda_bf16.h>
#include <cstdint>

// QuantumLSTM: T=1024, B=1024, IN=128, H=16.
// Phase 0: fold (b + theta) and split W_x into bf16 hi/lo.
// Phase 1: Z[t*B+b][gate*16+j] = x . Wx[j] + b + theta  via 3-pass bf16 mma.sync.
// Phase 2: sequential recurrence, 1 warp per batch element.

#define TT 1024
#define BB 1024
#define INDIM 128
#define HID 16
#define GD 64          // 4 gates * 16 units
#define DD 144         // IN + H
#define NROWS (TT * BB)
#define APAD 136       // padded smem row stride (bf16 elems) for bank-conflict-free frags

__device__ float g_Z[(size_t)NROWS * GD];          // 256 MB scratch
__device__ __nv_bfloat16 g_Whi[GD * INDIM];
__device__ __nv_bfloat16 g_Wlo[GD * INDIM];
__device__ float g_bias[GD];

// ---------------------------------------------------------------- phase 0
__global__ void prep_kernel(const float* __restrict__ Wf, const float* __restrict__ bf, const float* __restrict__ tf,
                            const float* __restrict__ Wi, const float* __restrict__ bi, const float* __restrict__ ti,
                            const float* __restrict__ Wg, const float* __restrict__ bg, const float* __restrict__ tg,
                            const float* __restrict__ Wo, const float* __restrict__ bo, const float* __restrict__ to_) {
    int idx = blockIdx.x * blockDim.x + threadIdx.x;
    if (idx < GD * INDIM) {
        int n = idx >> 7, k = idx & 127;
        int gate = n >> 4, j = n & 15;
        const float* W = (gate == 0) ? Wf : (gate == 1) ? Wi : (gate == 2) ? Wg : Wo;
        float w = W[j * DD + k];
        __nv_bfloat16 hi = __float2bfloat16(w);
        g_Whi[idx] = hi;
        g_Wlo[idx] = __float2bfloat16(w - __bfloat162float(hi));
    }
    if (idx < GD) {
        int gate = idx >> 4, j = idx & 15;
        const float* bp = (gate == 0) ? bf : (gate == 1) ? bi : (gate == 2) ? bg : bo;
        const float* tp = (gate == 0) ? tf : (gate == 1) ? ti : (gate == 2) ? tg : to_;
        g_bias[idx] = bp[j] + tp[j];
    }
}

// ---------------------------------------------------------------- phase 1
// Block: 256 threads (8 warps), tile M=128 rows, N=64, K=128.
// Each warp: 16 rows x 64 cols, 8 k-steps x 3 precision passes of m16n8k16 bf16 mma.
__global__ __launch_bounds__(256) void gemm_kernel(const float* __restrict__ A) {
    extern __shared__ __nv_bfloat16 smem[];
    __nv_bfloat16* Ah = smem;                    // 128 x APAD
    __nv_bfloat16* Al = Ah + 128 * APAD;
    __nv_bfloat16* Bh = Al + 128 * APAD;         // 64 x APAD
    __nv_bfloat16* Bl = Bh + GD * APAD;

    int tid = threadIdx.x;
    size_t row0 = (size_t)blockIdx.x * 128;

    // load + hi/lo split A tile (2 threads per row, 16 float4 each)
    {
        int r = tid >> 1;
        int c0 = (tid & 1) * 64;
        const float4* src = (const float4*)(A + (row0 + r) * INDIM + c0);
        __nv_bfloat16* ah = Ah + r * APAD + c0;
        __nv_bfloat16* al = Al + r * APAD + c0;
#pragma unroll
        for (int i = 0; i < 16; i++) {
            float4 v = src[i];
            float vv[4] = {v.x, v.y, v.z, v.w};
#pragma unroll
            for (int q = 0; q < 4; q++) {
                __nv_bfloat16 hi = __float2bfloat16(vv[q]);
                ah[i * 4 + q] = hi;
                al[i * 4 + q] = __float2bfloat16(vv[q] - __bfloat162float(hi));
            }
        }
    }
    // load pre-split weights
    for (int i = tid; i < GD * INDIM; i += 256) {
        int n = i >> 7, k = i & 127;
        Bh[n * APAD + k] = g_Whi[i];
        Bl[n * APAD + k] = g_Wlo[i];
    }
    __syncthreads();

    int warp = tid >> 5, lane = tid & 31;
    int qr = lane >> 2, qc = lane & 3;
    int mbase = warp * 16;

    float acc[8][4];
#pragma unroll
    for (int n = 0; n < 8; n++)
#pragma unroll
        for (int q = 0; q < 4; q++) acc[n][q] = 0.f;

#pragma unroll
    for (int pass = 0; pass < 3; pass++) {
        const __nv_bfloat16* As = (pass == 2) ? Al : Ah;
        const __nv_bfloat16* Bs = (pass == 1) ? Bl : Bh;
#pragma unroll
        for (int kk = 0; kk < 8; kk++) {
            int k0 = kk * 16;
            uint32_t a0 = *(const uint32_t*)(As + (mbase + qr) * APAD + k0 + qc * 2);
            uint32_t a1 = *(const uint32_t*)(As + (mbase + qr + 8) * APAD + k0 + qc * 2);
            uint32_t a2 = *(const uint32_t*)(As + (mbase + qr) * APAD + k0 + 8 + qc * 2);
            uint32_t a3 = *(const uint32_t*)(As + (mbase + qr + 8) * APAD + k0 + 8 + qc * 2);
#pragma unroll
            for (int nt = 0; nt < 8; nt++) {
                uint32_t b0 = *(const uint32_t*)(Bs + (nt * 8 + qr) * APAD + k0 + qc * 2);
                uint32_t b1 = *(const uint32_t*)(Bs + (nt * 8 + qr) * APAD + k0 + 8 + qc * 2);
                asm volatile(
                    "mma.sync.aligned.m16n8k16.row.col.f32.bf16.bf16.f32 "
                    "{%0,%1,%2,%3},{%4,%5,%6,%7},{%8,%9},{%0,%1,%2,%3};"
                    : "+f"(acc[nt][0]), "+f"(acc[nt][1]), "+f"(acc[nt][2]), "+f"(acc[nt][3])
                    : "r"(a0), "r"(a1), "r"(a2), "r"(a3), "r"(b0), "r"(b1));
            }
        }
    }

    // epilogue: + (b + theta), write Z
#pragma unroll
    for (int nt = 0; nt < 8; nt++) {
        int col = nt * 8 + qc * 2;
        float bias0 = g_bias[col], bias1 = g_bias[col + 1];
        size_t r1 = row0 + mbase + qr;
        float2 v0 = make_float2(acc[nt][0] + bias0, acc[nt][1] + bias1);
        float2 v1 = make_float2(acc[nt][2] + bias0, acc[nt][3] + bias1);
        *(float2*)(g_Z + r1 * GD + col) = v0;
        *(float2*)(g_Z + (r1 + 8) * GD + col) = v1;
    }
}

// ---------------------------------------------------------------- phase 2
__device__ __forceinline__ float ex2f(float x) { float y; asm("ex2.approx.f32 %0, %1;" : "=f"(y) : "f"(x)); return y; }
__device__ __forceinline__ float rcpf(float x) { float y; asm("rcp.approx.f32 %0, %1;" : "=f"(y) : "f"(x)); return y; }

// One warp per batch element. Lanes 0-15: unit j of gates (f, i).
// Lanes 16-31: unit j = lane-16 of gates (g, o).
__global__ __launch_bounds__(64) void lstm_kernel(
    const float* __restrict__ Wf, const float* __restrict__ Wi,
    const float* __restrict__ Wg, const float* __restrict__ Wo,
    float* __restrict__ out) {
    const unsigned FULL = 0xffffffffu;
    int lane = threadIdx.x & 31;
    int b = blockIdx.x * (blockDim.x >> 5) + (threadIdx.x >> 5);
    int grp = lane & 15;
    bool hi2 = lane >= 16;
    const float* WA = hi2 ? Wg : Wf;
    const float* WB = hi2 ? Wo : Wi;
    float wA[16], wB[16];
#pragma unroll
    for (int k = 0; k < 16; k++) {
        wA[k] = WA[grp * DD + INDIM + k];
        wB[k] = WB[grp * DD + INDIM + k];
    }
    float h = 0.f, c = 0.f;
    const float* zp = g_Z + (size_t)b * GD + lane + (hi2 ? 16 : 0);
    const size_t ts = (size_t)BB * GD;
    // 2-deep z prefetch to cover DRAM latency
    float z0 = zp[0], z1 = zp[16];
    float p0 = zp[ts], p1 = zp[ts + 16];
    float* outp = out + (size_t)b * HID + grp;

    for (int t = 0; t < TT; t++) {
        size_t off = (size_t)((t + 2 < TT) ? t + 2 : TT - 1) * ts;
        float n0 = zp[off], n1 = zp[off + 16];

        // recurrent part: a += h . Wh  (h broadcast via shfl from lanes 0-15)
        float a0 = z0, a1 = z1;
#pragma unroll
        for (int k = 0; k < 16; k++) {
            float hk = __shfl_sync(FULL, h, k);
            a0 = fmaf(wA[k], hk, a0);
            a1 = fmaf(wB[k], hk, a1);
        }
        // qgate: sin, segmented inclusive cumsum over 16 units, col0 += total
        float s0 = __sinf(a0), s1 = __sinf(a1);
#pragma unroll
        for (int d = 1; d < 16; d <<= 1) {
            float u0 = __shfl_up_sync(FULL, s0, d);
            float u1 = __shfl_up_sync(FULL, s1, d);
            if (grp >= d) { s0 += u0; s1 += u1; }
        }
        float tot0 = __shfl_sync(FULL, s0, lane | 15);
        float tot1 = __shfl_sync(FULL, s1, lane | 15);
        float q0 = (grp == 0) ? (s0 + tot0) : s0;
        float q1 = (grp == 0) ? (s1 + tot1) : s1;

        // activations: lo lanes sigmoid(f), sigmoid(i); hi lanes tanh(g), sigmoid(o)
        float scale0 = hi2 ? 2.885390082f : 1.442695041f;      // (2x)/ln2 vs x/ln2
        float r0 = rcpf(1.f + ex2f(-scale0 * q0));
        float act0 = hi2 ? (2.f * r0 - 1.f) : r0;
        float act1 = rcpf(1.f + ex2f(-1.442695041f * q1));

        // exchange halves: lo lanes fetch (g, o) from hi lanes
        float gg = __shfl_xor_sync(FULL, act0, 16);
        float oo = __shfl_xor_sync(FULL, act1, 16);

        // lo lanes: c = f*c + i*g ; h = o * tanh(c). hi lanes compute harmless junk.
        c = fmaf(act0, c, act1 * gg);
        float th = 2.f * rcpf(1.f + ex2f(-2.885390082f * c)) - 1.f;
        h = oo * th;

        if (!hi2) outp[(size_t)t * (BB * HID)] = h;
        z0 = p0; z1 = p1; p0 = n0; p1 = n1;
    }
    if (!hi2) {
        out[(size_t)TT * BB * HID + (size_t)b * HID + grp] = h;                       // hT
        out[(size_t)TT * BB * HID + (size_t)BB * HID + (size_t)b * HID + grp] = c;    // cT
    }
}

// ---------------------------------------------------------------- launch
extern "C" void kernel_launch(void* const* d_in, const int* in_sizes, int n_in,
                              void* d_out, int out_size) {
    const float* inputs = (const float*)d_in[0];
    const float* Wf = (const float*)d_in[1];
    const float* bf = (const float*)d_in[2];
    const float* tf = (const float*)d_in[3];
    const float* Wi = (const float*)d_in[4];
    const float* bi = (const float*)d_in[5];
    const float* ti = (const float*)d_in[6];
    const float* Wg = (const float*)d_in[7];
    const float* bg = (const float*)d_in[8];
    const float* tg = (const float*)d_in[9];
    const float* Wo = (const float*)d_in[10];
    const float* bo = (const float*)d_in[11];
    const float* to_ = (const float*)d_in[12];
    float* out = (float*)d_out;

    prep_kernel<<<32, 256>>>(Wf, bf, tf, Wi, bi, ti, Wg, bg, tg, Wo, bo, to_);

    int smem_bytes = (128 * APAD * 2 + GD * APAD * 2) * (int)sizeof(__nv_bfloat16);  // 104448
    cudaFuncSetAttribute(gemm_kernel, cudaFuncAttributeMaxDynamicSharedMemorySize, smem_bytes);
    gemm_kernel<<<NROWS / 128, 256, smem_bytes>>>(inputs);

    lstm_kernel<<<BB / 2, 64>>>(Wf, Wi, Wg, Wo, out);
}

// round 3
// speedup vs baseline: 1.6977x; 1.6977x over previous
#include <cuda_runtime.h>
#include <cuda_bf16.h>
#include <cstdint>

// QuantumLSTM: T=1024, B=1024, IN=128, H=16.
// Phase 0: fold (b + theta); split W_x into bf16 hi/lo.
// Phase 1: Z = x . Wx^T + (b+theta), 3-pass bf16 hi/lo via mma.sync (portable HMMA).
//          A frags from GMEM->regs, B frags via ldmatrix from smem.
// Phase 2: sequential recurrence, 1 warp per batch element.

#define TT 1024
#define BB 1024
#define INDIM 128
#define HID 16
#define GD 64
#define DD 144
#define NROWS (TT * BB)
#define BPITCH 136   // bf16 elems per B smem row (272B, conflict-free for LDSM)

__device__ float g_Z[(size_t)NROWS * GD];          // 256 MB scratch
__device__ __nv_bfloat16 g_Whi[GD * INDIM];
__device__ __nv_bfloat16 g_Wlo[GD * INDIM];
__device__ float g_bias[GD];

// ---------------------------------------------------------------- phase 0
__global__ void prep_kernel(const float* __restrict__ Wf, const float* __restrict__ bf, const float* __restrict__ tf,
                            const float* __restrict__ Wi, const float* __restrict__ bi, const float* __restrict__ ti,
                            const float* __restrict__ Wg, const float* __restrict__ bg, const float* __restrict__ tg,
                            const float* __restrict__ Wo, const float* __restrict__ bo, const float* __restrict__ to_) {
    int idx = blockIdx.x * blockDim.x + threadIdx.x;
    if (idx < GD * INDIM) {
        int n = idx >> 7, k = idx & 127;
        int gate = n >> 4, j = n & 15;
        const float* W = (gate == 0) ? Wf : (gate == 1) ? Wi : (gate == 2) ? Wg : Wo;
        float w = W[j * DD + k];
        __nv_bfloat16 hi = __float2bfloat16(w);
        g_Whi[idx] = hi;
        g_Wlo[idx] = __float2bfloat16(w - __bfloat162float(hi));
    }
    if (idx < GD) {
        int gate = idx >> 4, j = idx & 15;
        const float* bp = (gate == 0) ? bf : (gate == 1) ? bi : (gate == 2) ? bg : bo;
        const float* tp = (gate == 0) ? tf : (gate == 1) ? ti : (gate == 2) ? tg : to_;
        g_bias[idx] = bp[j] + tp[j];
    }
}

// ---------------------------------------------------------------- phase 1
static __device__ __forceinline__ void split2(float x, float y, uint32_t& hi, uint32_t& lo) {
    __nv_bfloat162 h2 = __floats2bfloat162_rn(x, y);
    hi = *(uint32_t*)&h2;
    __nv_bfloat162 l2 = __floats2bfloat162_rn(x - __bfloat162float(h2.x),
                                              y - __bfloat162float(h2.y));
    lo = *(uint32_t*)&l2;
}
static __device__ __forceinline__ void mma16816(float* acc, uint32_t a0, uint32_t a1,
                                                uint32_t a2, uint32_t a3,
                                                uint32_t b0, uint32_t b1) {
    asm volatile(
        "mma.sync.aligned.m16n8k16.row.col.f32.bf16.bf16.f32 "
        "{%0,%1,%2,%3},{%4,%5,%6,%7},{%8,%9},{%0,%1,%2,%3};"
        : "+f"(acc[0]), "+f"(acc[1]), "+f"(acc[2]), "+f"(acc[3])
        : "r"(a0), "r"(a1), "r"(a2), "r"(a3), "r"(b0), "r"(b1));
}
static __device__ __forceinline__ void ldsm4(uint32_t addr, uint32_t& r0, uint32_t& r1,
                                             uint32_t& r2, uint32_t& r3) {
    asm volatile("ldmatrix.sync.aligned.m8n8.x4.shared.b16 {%0,%1,%2,%3}, [%4];"
                 : "=r"(r0), "=r"(r1), "=r"(r2), "=r"(r3) : "r"(addr));
}

// Block: 256 threads (8 warps). Tile M=128 (16 rows/warp), N=64, K=128.
__global__ __launch_bounds__(256) void gemm_kernel(const float* __restrict__ A) {
    __shared__ __nv_bfloat16 Bh[GD * BPITCH];
    __shared__ __nv_bfloat16 Bl[GD * BPITCH];
    __shared__ float bias_s[GD];

    int tid = threadIdx.x;
    int warp = tid >> 5, lane = tid & 31;
    int qr = lane >> 2, qc = lane & 3;
    size_t row0 = (size_t)blockIdx.x * 128;

    // stage pre-split weights (8-elem chunks keep 16B alignment in padded rows)
#pragma unroll
    for (int i = 0; i < 4; i++) {
        int e = tid + 256 * i;             // 0..1023, 1024 chunks of 8 bf16
        int n = e >> 4, kq = e & 15;
        *(uint4*)(Bh + n * BPITCH + kq * 8) = *(const uint4*)(g_Whi + n * INDIM + kq * 8);
        *(uint4*)(Bl + n * BPITCH + kq * 8) = *(const uint4*)(g_Wlo + n * INDIM + kq * 8);
    }
    if (tid < GD) bias_s[tid] = g_bias[tid];

    // ldmatrix base addresses: group g covers nt = 2g, 2g+1
    // lane tile = lane>>3: t0 rows n0-7@k0, t1 n0-7@k8, t2 n8-15@k0, t3 n8-15@k8
    int tile = lane >> 3, rrow = lane & 7;
    uint32_t lrow_off = (uint32_t)(((tile >> 1) & 1) * 8 + rrow) * (BPITCH * 2) + (tile & 1) * 16;
    uint32_t bhb = (uint32_t)__cvta_generic_to_shared(Bh) + lrow_off;
    uint32_t blb = (uint32_t)__cvta_generic_to_shared(Bl) + lrow_off;

    const float* aptr = A + (row0 + warp * 16 + qr) * INDIM + qc * 2;

    float acc[8][4];
#pragma unroll
    for (int n = 0; n < 8; n++)
#pragma unroll
        for (int q = 0; q < 4; q++) acc[n][q] = 0.f;

    __syncthreads();

#pragma unroll
    for (int kk = 0; kk < 8; kk++) {
        int k0 = kk * 16;
        // A fragment: 4x LDG.64, fully coalesced 32B sectors
        float2 v00 = *(const float2*)(aptr + k0);
        float2 v10 = *(const float2*)(aptr + 8 * INDIM + k0);
        float2 v01 = *(const float2*)(aptr + k0 + 8);
        float2 v11 = *(const float2*)(aptr + 8 * INDIM + k0 + 8);
        uint32_t ah[4], al[4];
        split2(v00.x, v00.y, ah[0], al[0]);
        split2(v10.x, v10.y, ah[1], al[1]);
        split2(v01.x, v01.y, ah[2], al[2]);
        split2(v11.x, v11.y, ah[3], al[3]);

#pragma unroll
        for (int g = 0; g < 4; g++) {
            uint32_t koff = (uint32_t)(g * 16 * (BPITCH * 2) + kk * 32);
            uint32_t h0, h1, h2, h3, l0, l1, l2, l3;
            ldsm4(bhb + koff, h0, h1, h2, h3);
            ldsm4(blb + koff, l0, l1, l2, l3);
            // hi*hi
            mma16816(acc[2 * g],     ah[0], ah[1], ah[2], ah[3], h0, h1);
            mma16816(acc[2 * g + 1], ah[0], ah[1], ah[2], ah[3], h2, h3);
            // lo*hi
            mma16816(acc[2 * g],     al[0], al[1], al[2], al[3], h0, h1);
            mma16816(acc[2 * g + 1], al[0], al[1], al[2], al[3], h2, h3);
            // hi*lo
            mma16816(acc[2 * g],     ah[0], ah[1], ah[2], ah[3], l0, l1);
            mma16816(acc[2 * g + 1], ah[0], ah[1], ah[2], ah[3], l2, l3);
        }
    }

    // epilogue: + (b + theta), write Z
#pragma unroll
    for (int nt = 0; nt < 8; nt++) {
        int col = nt * 8 + qc * 2;
        float bias0 = bias_s[col], bias1 = bias_s[col + 1];
        size_t r1 = row0 + warp * 16 + qr;
        float2 v0 = make_float2(acc[nt][0] + bias0, acc[nt][1] + bias1);
        float2 v1 = make_float2(acc[nt][2] + bias0, acc[nt][3] + bias1);
        *(float2*)(g_Z + r1 * GD + col) = v0;
        *(float2*)(g_Z + (r1 + 8) * GD + col) = v1;
    }
}

// ---------------------------------------------------------------- phase 2
__device__ __forceinline__ float ex2f(float x) { float y; asm("ex2.approx.f32 %0, %1;" : "=f"(y) : "f"(x)); return y; }
__device__ __forceinline__ float rcpf(float x) { float y; asm("rcp.approx.f32 %0, %1;" : "=f"(y) : "f"(x)); return y; }

// One warp per batch element. Lanes 0-15: (f,i) unit j; lanes 16-31: (g,o) unit j.
__global__ __launch_bounds__(64) void lstm_kernel(
    const float* __restrict__ Wf, const float* __restrict__ Wi,
    const float* __restrict__ Wg, const float* __restrict__ Wo,
    float* __restrict__ out) {
    const unsigned FULL = 0xffffffffu;
    int lane = threadIdx.x & 31;
    int b = blockIdx.x * (blockDim.x >> 5) + (threadIdx.x >> 5);
    int grp = lane & 15;
    bool hi2 = lane >= 16;
    const float* WA = hi2 ? Wg : Wf;
    const float* WB = hi2 ? Wo : Wi;
    float wA[16], wB[16];
#pragma unroll
    for (int k = 0; k < 16; k++) {
        wA[k] = WA[grp * DD + INDIM + k];
        wB[k] = WB[grp * DD + INDIM + k];
    }
    float h = 0.f, c = 0.f;
    const float* zp = g_Z + (size_t)b * GD + lane + (hi2 ? 16 : 0);
    const size_t ts = (size_t)BB * GD;
    float z0 = zp[0], z1 = zp[16];
    float p0 = zp[ts], p1 = zp[ts + 16];
    float* outp = out + (size_t)b * HID + grp;

    for (int t = 0; t < TT; t++) {
        size_t off = (size_t)((t + 2 < TT) ? t + 2 : TT - 1) * ts;
        float n0 = zp[off], n1 = zp[off + 16];

        // h broadcast (all shfls independent of each other)
        float hk[16];
#pragma unroll
        for (int k = 0; k < 16; k++) hk[k] = __shfl_sync(FULL, h, k);

        // tree-form dot products: depth ~4 FMA + 2 ADD instead of 16 serial FMA
        float a0, a1;
        {
            float q0 = wA[0] * hk[0], q1 = wA[4] * hk[4], q2 = wA[8] * hk[8], q3 = wA[12] * hk[12];
            float r0 = wB[0] * hk[0], r1 = wB[4] * hk[4], r2 = wB[8] * hk[8], r3 = wB[12] * hk[12];
#pragma unroll
            for (int k = 1; k < 4; k++) {
                q0 = fmaf(wA[k], hk[k], q0);       r0 = fmaf(wB[k], hk[k], r0);
                q1 = fmaf(wA[4 + k], hk[4 + k], q1);   r1 = fmaf(wB[4 + k], hk[4 + k], r1);
                q2 = fmaf(wA[8 + k], hk[8 + k], q2);   r2 = fmaf(wB[8 + k], hk[8 + k], r2);
                q3 = fmaf(wA[12 + k], hk[12 + k], q3); r3 = fmaf(wB[12 + k], hk[12 + k], r3);
            }
            a0 = z0 + ((q0 + q1) + (q2 + q3));
            a1 = z1 + ((r0 + r1) + (r2 + r3));
        }

        float s0 = __sinf(a0), s1 = __sinf(a1);
#pragma unroll
        for (int d = 1; d < 16; d <<= 1) {
            float u0 = __shfl_up_sync(FULL, s0, d);
            float u1 = __shfl_up_sync(FULL, s1, d);
            if (grp >= d) { s0 += u0; s1 += u1; }
        }
        float tot0 = __shfl_sync(FULL, s0, lane | 15);
        float tot1 = __shfl_sync(FULL, s1, lane | 15);
        float q0 = (grp == 0) ? (s0 + tot0) : s0;
        float q1 = (grp == 0) ? (s1 + tot1) : s1;

        float scale0 = hi2 ? 2.885390082f : 1.442695041f;
        float r0 = rcpf(1.f + ex2f(-scale0 * q0));
        float act0 = hi2 ? (2.f * r0 - 1.f) : r0;
        float act1 = rcpf(1.f + ex2f(-1.442695041f * q1));

        float gg = __shfl_xor_sync(FULL, act0, 16);
        float oo = __shfl_xor_sync(FULL, act1, 16);

        c = fmaf(act0, c, act1 * gg);
        float th = 2.f * rcpf(1.f + ex2f(-2.885390082f * c)) - 1.f;
        h = oo * th;

        if (!hi2) outp[(size_t)t * (BB * HID)] = h;
        z0 = p0; z1 = p1; p0 = n0; p1 = n1;
    }
    if (!hi2) {
        out[(size_t)TT * BB * HID + (size_t)b * HID + grp] = h;
        out[(size_t)TT * BB * HID + (size_t)BB * HID + (size_t)b * HID + grp] = c;
    }
}

// ---------------------------------------------------------------- launch
extern "C" void kernel_launch(void* const* d_in, const int* in_sizes, int n_in,
                              void* d_out, int out_size) {
    const float* inputs = (const float*)d_in[0];
    const float* Wf = (const float*)d_in[1];
    const float* bf = (const float*)d_in[2];
    const float* tf = (const float*)d_in[3];
    const float* Wi = (const float*)d_in[4];
    const float* bi = (const float*)d_in[5];
    const float* ti = (const float*)d_in[6];
    const float* Wg = (const float*)d_in[7];
    const float* bg = (const float*)d_in[8];
    const float* tg = (const float*)d_in[9];
    const float* Wo = (const float*)d_in[10];
    const float* bo = (const float*)d_in[11];
    const float* to_ = (const float*)d_in[12];
    float* out = (float*)d_out;

    prep_kernel<<<32, 256>>>(Wf, bf, tf, Wi, bi, ti, Wg, bg, tg, Wo, bo, to_);
    gemm_kernel<<<NROWS / 128, 256>>>(inputs);
    lstm_kernel<<<BB / 2, 64>>>(Wf, Wi, Wg, Wo, out);
}

// round 5
// speedup vs baseline: 1.7169x; 1.0113x over previous
#include <cuda_runtime.h>
#include <cuda_bf16.h>
#include <cstdint>

// QuantumLSTM: T=1024, B=1024, IN=128, H=16.
// Phase 1 (gemm): Z = x . Wx^T + (b+theta), 3-pass bf16 hi/lo via mma.sync.
//                 W split + bias folded into the gemm (no prep kernel).
// Phase 2 (lstm): sequential recurrence, 1 warp per batch element.

#define TT 1024
#define BB 1024
#define INDIM 128
#define HID 16
#define GD 64
#define DD 144
#define NROWS (TT * BB)
#define BPITCH 136   // bf16 elems per B smem row (272B, conflict-free for LDSM)

__device__ float g_Z[(size_t)NROWS * GD];          // 256 MB scratch

// ---------------------------------------------------------------- helpers
static __device__ __forceinline__ void split2(float x, float y, uint32_t& hi, uint32_t& lo) {
    __nv_bfloat162 h2 = __floats2bfloat162_rn(x, y);
    hi = *(uint32_t*)&h2;
    __nv_bfloat162 l2 = __floats2bfloat162_rn(x - __bfloat162float(h2.x),
                                              y - __bfloat162float(h2.y));
    lo = *(uint32_t*)&l2;
}
static __device__ __forceinline__ void mma16816(float* acc, uint32_t a0, uint32_t a1,
                                                uint32_t a2, uint32_t a3,
                                                uint32_t b0, uint32_t b1) {
    asm volatile(
        "mma.sync.aligned.m16n8k16.row.col.f32.bf16.bf16.f32 "
        "{%0,%1,%2,%3},{%4,%5,%6,%7},{%8,%9},{%0,%1,%2,%3};"
        : "+f"(acc[0]), "+f"(acc[1]), "+f"(acc[2]), "+f"(acc[3])
        : "r"(a0), "r"(a1), "r"(a2), "r"(a3), "r"(b0), "r"(b1));
}
static __device__ __forceinline__ void ldsm4(uint32_t addr, uint32_t& r0, uint32_t& r1,
                                             uint32_t& r2, uint32_t& r3) {
    asm volatile("ldmatrix.sync.aligned.m8n8.x4.shared.b16 {%0,%1,%2,%3}, [%4];"
                 : "=r"(r0), "=r"(r1), "=r"(r2), "=r"(r3) : "r"(addr));
}

// ---------------------------------------------------------------- phase 1
// Block: 256 threads (8 warps). Tile M=128 (16 rows/warp), N=64, K=128.
__global__ __launch_bounds__(256) void gemm_kernel(
    const float* __restrict__ A,
    const float* __restrict__ Wf, const float* __restrict__ bf, const float* __restrict__ tf,
    const float* __restrict__ Wi, const float* __restrict__ bi, const float* __restrict__ ti,
    const float* __restrict__ Wg, const float* __restrict__ bg, const float* __restrict__ tg,
    const float* __restrict__ Wo, const float* __restrict__ bo, const float* __restrict__ to_) {
    __shared__ __nv_bfloat16 Bh[GD * BPITCH];
    __shared__ __nv_bfloat16 Bl[GD * BPITCH];
    __shared__ float bias_s[GD];

    int tid = threadIdx.x;
    int warp = tid >> 5, lane = tid & 31;
    int qr = lane >> 2, qc = lane & 3;
    size_t row0 = (size_t)blockIdx.x * 128;

    // stage weights: load fp32 W, hi/lo split, write smem (8-elem chunks)
#pragma unroll
    for (int i = 0; i < 4; i++) {
        int e = tid + 256 * i;             // 1024 chunks of 8 bf16
        int n = e >> 4, kq = (e & 15) * 8;
        int gate = n >> 4, j = n & 15;
        const float* W = (gate == 0) ? Wf : (gate == 1) ? Wi : (gate == 2) ? Wg : Wo;
        float4 u0 = *(const float4*)(W + j * DD + kq);
        float4 u1 = *(const float4*)(W + j * DD + kq + 4);
        uint32_t h[4], l[4];
        split2(u0.x, u0.y, h[0], l[0]);
        split2(u0.z, u0.w, h[1], l[1]);
        split2(u1.x, u1.y, h[2], l[2]);
        split2(u1.z, u1.w, h[3], l[3]);
        *(uint4*)(Bh + n * BPITCH + kq) = make_uint4(h[0], h[1], h[2], h[3]);
        *(uint4*)(Bl + n * BPITCH + kq) = make_uint4(l[0], l[1], l[2], l[3]);
    }
    if (tid < GD) {
        int gate = tid >> 4, j = tid & 15;
        const float* bp = (gate == 0) ? bf : (gate == 1) ? bi : (gate == 2) ? bg : bo;
        const float* tp = (gate == 0) ? tf : (gate == 1) ? ti : (gate == 2) ? tg : to_;
        bias_s[tid] = bp[j] + tp[j];
    }

    // ldmatrix base addresses: group g covers nt = 2g, 2g+1
    int tile = lane >> 3, rrow = lane & 7;
    uint32_t lrow_off = (uint32_t)(((tile >> 1) & 1) * 8 + rrow) * (BPITCH * 2) + (tile & 1) * 16;
    uint32_t bhb = (uint32_t)__cvta_generic_to_shared(Bh) + lrow_off;
    uint32_t blb = (uint32_t)__cvta_generic_to_shared(Bl) + lrow_off;

    const float* aptr = A + (row0 + warp * 16 + qr) * INDIM + qc * 2;

    float acc[8][4];
#pragma unroll
    for (int n = 0; n < 8; n++)
#pragma unroll
        for (int q = 0; q < 4; q++) acc[n][q] = 0.f;

    __syncthreads();

    // software-pipelined A fragment loads
    float2 v[4], vn[4];
    v[0] = *(const float2*)(aptr);
    v[1] = *(const float2*)(aptr + 8 * INDIM);
    v[2] = *(const float2*)(aptr + 8);
    v[3] = *(const float2*)(aptr + 8 * INDIM + 8);

#pragma unroll
    for (int kk = 0; kk < 8; kk++) {
        if (kk < 7) {
            int k1 = (kk + 1) * 16;
            vn[0] = *(const float2*)(aptr + k1);
            vn[1] = *(const float2*)(aptr + 8 * INDIM + k1);
            vn[2] = *(const float2*)(aptr + k1 + 8);
            vn[3] = *(const float2*)(aptr + 8 * INDIM + k1 + 8);
        }
        uint32_t ah[4], al[4];
        split2(v[0].x, v[0].y, ah[0], al[0]);
        split2(v[1].x, v[1].y, ah[1], al[1]);
        split2(v[2].x, v[2].y, ah[2], al[2]);
        split2(v[3].x, v[3].y, ah[3], al[3]);

#pragma unroll
        for (int g = 0; g < 4; g++) {
            uint32_t koff = (uint32_t)(g * 16 * (BPITCH * 2) + kk * 32);
            uint32_t h0, h1, h2, h3, l0, l1, l2, l3;
            ldsm4(bhb + koff, h0, h1, h2, h3);
            ldsm4(blb + koff, l0, l1, l2, l3);
            mma16816(acc[2 * g],     ah[0], ah[1], ah[2], ah[3], h0, h1);
            mma16816(acc[2 * g + 1], ah[0], ah[1], ah[2], ah[3], h2, h3);
            mma16816(acc[2 * g],     al[0], al[1], al[2], al[3], h0, h1);
            mma16816(acc[2 * g + 1], al[0], al[1], al[2], al[3], h2, h3);
            mma16816(acc[2 * g],     ah[0], ah[1], ah[2], ah[3], l0, l1);
            mma16816(acc[2 * g + 1], ah[0], ah[1], ah[2], ah[3], l2, l3);
        }
#pragma unroll
        for (int q = 0; q < 4; q++) v[q] = vn[q];
    }

    // epilogue: + (b + theta), write Z
#pragma unroll
    for (int nt = 0; nt < 8; nt++) {
        int col = nt * 8 + qc * 2;
        float bias0 = bias_s[col], bias1 = bias_s[col + 1];
        size_t r1 = row0 + warp * 16 + qr;
        float2 v0 = make_float2(acc[nt][0] + bias0, acc[nt][1] + bias1);
        float2 v1 = make_float2(acc[nt][2] + bias0, acc[nt][3] + bias1);
        *(float2*)(g_Z + r1 * GD + col) = v0;
        *(float2*)(g_Z + (r1 + 8) * GD + col) = v1;
    }
}

// ---------------------------------------------------------------- phase 2
__device__ __forceinline__ float ex2f(float x) { float y; asm("ex2.approx.f32 %0, %1;" : "=f"(y) : "f"(x)); return y; }
__device__ __forceinline__ float rcpf(float x) { float y; asm("rcp.approx.f32 %0, %1;" : "=f"(y) : "f"(x)); return y; }

// One warp per batch element. Lanes 0-15: (f,i) unit j; lanes 16-31: (g,o) unit j.
__global__ __launch_bounds__(64) void lstm_kernel(
    const float* __restrict__ Wf, const float* __restrict__ Wi,
    const float* __restrict__ Wg, const float* __restrict__ Wo,
    float* __restrict__ out) {
    const unsigned FULL = 0xffffffffu;
    int lane = threadIdx.x & 31;
    int b = blockIdx.x * (blockDim.x >> 5) + (threadIdx.x >> 5);
    int grp = lane & 15;
    bool hi2 = lane >= 16;
    const float* WA = hi2 ? Wg : Wf;
    const float* WB = hi2 ? Wo : Wi;
    float wA[16], wB[16];
#pragma unroll
    for (int k = 0; k < 16; k++) {
        wA[k] = WA[grp * DD + INDIM + k];
        wB[k] = WB[grp * DD + INDIM + k];
    }
    float h = 0.f, c = 0.f;
    const float* zp = g_Z + (size_t)b * GD + lane + (hi2 ? 16 : 0);
    const size_t ts = (size_t)BB * GD;
    float z0 = zp[0], z1 = zp[16];
    float p0 = zp[ts], p1 = zp[ts + 16];
    float* outp = out + (size_t)b * HID + grp;

    for (int t = 0; t < TT; t++) {
        size_t off = (size_t)((t + 2 < TT) ? t + 2 : TT - 1) * ts;
        float n0 = zp[off], n1 = zp[off + 16];

        // h broadcast (independent shfls, pipelined)
        float hk[16];
#pragma unroll
        for (int k = 0; k < 16; k++) hk[k] = __shfl_sync(FULL, h, k);

        // tree-form dot products
        float a0, a1;
        {
            float q0 = wA[0] * hk[0], q1 = wA[4] * hk[4], q2 = wA[8] * hk[8], q3 = wA[12] * hk[12];
            float r0 = wB[0] * hk[0], r1 = wB[4] * hk[4], r2 = wB[8] * hk[8], r3 = wB[12] * hk[12];
#pragma unroll
            for (int k = 1; k < 4; k++) {
                q0 = fmaf(wA[k], hk[k], q0);           r0 = fmaf(wB[k], hk[k], r0);
                q1 = fmaf(wA[4 + k], hk[4 + k], q1);   r1 = fmaf(wB[4 + k], hk[4 + k], r1);
                q2 = fmaf(wA[8 + k], hk[8 + k], q2);   r2 = fmaf(wB[8 + k], hk[8 + k], r2);
                q3 = fmaf(wA[12 + k], hk[12 + k], q3); r3 = fmaf(wB[12 + k], hk[12 + k], r3);
            }
            a0 = z0 + ((q0 + q1) + (q2 + q3));
            a1 = z1 + ((r0 + r1) + (r2 + r3));
        }

        // qgate: sin, then butterfly that yields BOTH inclusive prefix and total
        float s0 = __sinf(a0), s1 = __sinf(a1);
        float x0 = s0, x1 = s1;                 // running block sums
#pragma unroll
        for (int d = 1; d < 16; d <<= 1) {
            float y0 = __shfl_xor_sync(FULL, x0, d);
            float y1 = __shfl_xor_sync(FULL, x1, d);
            if (grp & d) { s0 += y0; s1 += y1; }
            x0 += y0; x1 += y1;
        }
        // s = inclusive prefix within 16-group, x = group total
        float q0 = (grp == 0) ? (s0 + x0) : s0;
        float q1 = (grp == 0) ? (s1 + x1) : s1;

        float scale0 = hi2 ? 2.885390082f : 1.442695041f;
        float r0 = rcpf(1.f + ex2f(-scale0 * q0));
        float act0 = hi2 ? (2.f * r0 - 1.f) : r0;            // tanh(g) / sigmoid(f)
        float act1 = rcpf(1.f + ex2f(-1.442695041f * q1));   // sigmoid(i) / sigmoid(o)

        float gg = __shfl_xor_sync(FULL, act0, 16);
        float oo = __shfl_xor_sync(FULL, act1, 16);

        c = fmaf(act0, c, act1 * gg);
        float th = 2.f * rcpf(1.f + ex2f(-2.885390082f * c)) - 1.f;
        h = oo * th;

        if (!hi2) outp[(size_t)t * (BB * HID)] = h;
        z0 = p0; z1 = p1; p0 = n0; p1 = n1;
    }
    if (!hi2) {
        out[(size_t)TT * BB * HID + (size_t)b * HID + grp] = h;
        out[(size_t)TT * BB * HID + (size_t)BB * HID + (size_t)b * HID + grp] = c;
    }
}

// ---------------------------------------------------------------- launch
extern "C" void kernel_launch(void* const* d_in, const int* in_sizes, int n_in,
                              void* d_out, int out_size) {
    const float* inputs = (const float*)d_in[0];
    const float* Wf = (const float*)d_in[1];
    const float* bf = (const float*)d_in[2];
    const float* tf = (const float*)d_in[3];
    const float* Wi = (const float*)d_in[4];
    const float* bi = (const float*)d_in[5];
    const float* ti = (const float*)d_in[6];
    const float* Wg = (const float*)d_in[7];
    const float* bg = (const float*)d_in[8];
    const float* tg = (const float*)d_in[9];
    const float* Wo = (const float*)d_in[10];
    const float* bo = (const float*)d_in[11];
    const float* to_ = (const float*)d_in[12];
    float* out = (float*)d_out;

    gemm_kernel<<<NROWS / 128, 256>>>(inputs, Wf, bf, tf, Wi, bi, ti,
                                      Wg, bg, tg, Wo, bo, to_);
    lstm_kernel<<<BB / 2, 64>>>(Wf, Wi, Wg, Wo, out);
}